// round 13
// baseline (speedup 1.0000x reference)
#include <cuda_runtime.h>
#include <cuda_bf16.h>
#include <cstdint>

#define BB 2
#define SS 1024
#define HID 4096
#define HH 32
#define QL 1536
#define KVL 512
#define ROPE 64
#define DD 576              // KVL + ROPE
#define MM (BB*SS)          // 2048
#define N12 2112            // QL + DD (merged proj width)

// ---------------- fp32 scratch ----------------
__device__ __align__(16) float g_buf12[(size_t)MM * N12];   // [qa_raw | ckv]
__device__ __align__(16) float g_bufA[(size_t)MM * 2048];   // qpe_raw
__device__ __align__(16) float g_keys[(size_t)MM * KVL];    // kva fp32 (for ekva transpose)
__device__ __align__(16) float g_scores[(size_t)64 * SS * SS];

// ---------------- bf16 expanded operands (x3 along K for hi/lo split) --------
__device__ __align__(1024) __nv_bfloat16 e_hidden[(size_t)2048 * 12288];
__device__ __align__(1024) __nv_bfloat16 e_w12  [(size_t)N12 * 12288];   // [wqa rows | wkva rows]
__device__ __align__(1024) __nv_bfloat16 e_qa   [(size_t)2048 * 4608];
__device__ __align__(1024) __nv_bfloat16 e_qrope[(size_t)2048 * 4608];
__device__ __align__(1024) __nv_bfloat16 e_fqk  [(size_t)32 * 512 * 4608];
__device__ __align__(1024) __nv_bfloat16 e_query[(size_t)65536 * 1728];
__device__ __align__(1024) __nv_bfloat16 e_keys [(size_t)2048 * 1728];
__device__ __align__(1024) __nv_bfloat16 e_scores[(size_t)65536 * 3072];
__device__ __align__(1024) __nv_bfloat16 e_kva  [(size_t)2 * 512 * 3072];
__device__ __align__(1024) __nv_bfloat16 e_ctx  [(size_t)65536 * 1536];
__device__ __align__(1024) __nv_bfloat16 e_vup  [(size_t)32 * 128 * 1536];
__device__ __align__(1024) __nv_bfloat16 e_attout[(size_t)2048 * 12288];
__device__ __align__(1024) __nv_bfloat16 e_wo   [(size_t)4096 * 12288];

// ---------------- helpers ----------------
__device__ __forceinline__ uint32_t smem_u32(const void* p) {
    uint32_t a;
    asm("{ .reg .u64 t; cvta.to.shared.u64 t, %1; cvt.u32.u64 %0, t; }" : "=r"(a) : "l"(p));
    return a;
}
__device__ __forceinline__ void split2(float x, __nv_bfloat16& hi, __nv_bfloat16& lo) {
    hi = __float2bfloat16(x);
    lo = __float2bfloat16(x - __bfloat162float(hi));
}
__device__ __forceinline__ void rope_pair(float x0, float x1, float pos, int j,
                                          float& o0, float& o1)
{
    float inv = expf(-(float)j * 0.28782313662425581f);  // ln(10000)/32
    float f = pos * inv;
    float c = cosf(f), s = sinf(f);
    o0 = x0 * c - x1 * s;
    o1 = x1 * c + x0 * s;
}
__device__ __forceinline__ void store_exp(__nv_bfloat16* o, long long idx, int segS,
                                          float v, int role)
{
    __nv_bfloat16 hi, lo; split2(v, hi, lo);
    o[idx] = hi;
    o[idx + segS]     = role ? hi : lo;
    o[idx + 2 * segS] = role ? lo : hi;
}

#define LDMX4(d0,d1,d2,d3,addr) \
    asm volatile("ldmatrix.sync.aligned.m8n8.x4.shared.b16 {%0,%1,%2,%3}, [%4];" \
        : "=r"(d0), "=r"(d1), "=r"(d2), "=r"(d3) : "r"(addr))

#define MMA16816(c, a, b0, b1) \
    asm volatile("mma.sync.aligned.m16n8k16.row.col.f32.bf16.bf16.f32 " \
        "{%0,%1,%2,%3}, {%4,%5,%6,%7}, {%8,%9}, {%0,%1,%2,%3};" \
        : "+f"((c)[0]), "+f"((c)[1]), "+f"((c)[2]), "+f"((c)[3]) \
        : "r"((a)[0]), "r"((a)[1]), "r"((a)[2]), "r"((a)[3]), "r"(b0), "r"(b1))

// ---------------- HMMA bf16 GEMM: C[M,N] = A[M,K] @ B[N,K]^T (both K-major) --
// 128x128 CTA, BK=32, 512 thr, 16 warps (4m x 4n), warp tile 32x32, 2 CTAs/SM
// (8 warps/SMSP for latency hiding; acc 32 regs/thread).
// 5-stage cp.async ring, ONE __syncthreads per chunk. Requires nChunks >= 3.
// OUTBF16=0: fp32 C. OUTBF16=1: bf16 3-term A-role hi|lo|hi at +{0,segS,2segS}.
// CAUSAL: 0 none; 1 skip bx>by; 2 token-chunk skip (kLimit=(by+1)*128).
// rowMul!=0: epilogue row remap orow = (row & 1023) + (row >> 10) * rowMul.
#define SSTRIDE 40
#define BUFH (128 * SSTRIDE)        // halves per operand per stage
#define STAGEH (2 * BUFH)           // A + B per stage
#define NSTAGE 5
#define GSMEM_SZ (NSTAGE * STAGEH * 2)   // 102400 bytes

template<int CAUSAL, int OUTBF16>
__global__ __launch_bounds__(512, 2)
void mma_gemm(const __nv_bfloat16* __restrict__ A,
              const __nv_bfloat16* __restrict__ B,
              void* __restrict__ Cv,
              int M, int N, int K, int lda, int ldb, int ldc, int segS,
              long long sAo, long long sAi, long long sBo, long long sBi,
              long long sCo, long long sCi, int innerCnt, int tokMask, int rowMul)
{
    if (CAUSAL == 1 && blockIdx.x > blockIdx.y) return;

    extern __shared__ __align__(16) char dsm[];

    int z = blockIdx.z;
    int outer = z / innerCnt, inner = z - outer * innerCnt;
    A += outer * sAo + inner * sAi;
    B += outer * sBo + inner * sBi;
    long long coff = outer * sCo + inner * sCi;

    int tid = threadIdx.x, lane = tid & 31, wid = tid >> 5;
    int warp_m = wid & 3, warp_n = wid >> 2;     // 4 x 4
    int bm = blockIdx.y * 128, bn = blockIdx.x * 128;

    uint32_t sBase = smem_u32(dsm);

    int per = 0, nChunks;
    int seg = tokMask + 1;
    if (CAUSAL == 2) {
        int kl = (blockIdx.y + 1) * 128;
        if (kl > seg) kl = seg;
        per = kl >> 5;
        nChunks = (K / seg) * per;
    } else {
        nChunks = K >> 5;
    }

    auto k0_of = [&](int ci) -> int {
        if (CAUSAL == 2) return (ci / per) * seg + (ci % per) * 32;
        return ci * 32;
    };

    int frow = tid >> 2, fc = tid & 3;           // one cp.async per thread per operand
    auto issue = [&](int stage, int k0) {
        uint32_t aB = sBase + (uint32_t)(stage * STAGEH) * 2;
        uint32_t bB = aB + BUFH * 2;
        {
            const __nv_bfloat16* src = A + (size_t)(bm + frow) * lda + k0 + fc * 8;
            uint32_t dst = aB + (uint32_t)(frow * SSTRIDE + fc * 8) * 2;
            asm volatile("cp.async.cg.shared.global [%0], [%1], 16;"
                         :: "r"(dst), "l"(src));
        }
        {
            int ok = (bn + frow) < N;
            const __nv_bfloat16* src = B + (size_t)(bn + (ok ? frow : 0)) * ldb + k0 + fc * 8;
            uint32_t dst = bB + (uint32_t)(frow * SSTRIDE + fc * 8) * 2;
            int sz = ok ? 16 : 0;
            asm volatile("cp.async.cg.shared.global [%0], [%1], 16, %2;"
                         :: "r"(dst), "l"(src), "r"(sz));
        }
        asm volatile("cp.async.commit_group;" ::: "memory");
    };

    float acc[2][4][4];
    #pragma unroll
    for (int i = 0; i < 2; i++)
        #pragma unroll
        for (int j = 0; j < 4; j++)
            #pragma unroll
            for (int q = 0; q < 4; q++) acc[i][j][q] = 0.f;

    int g = lane >> 3, r = lane & 7;

    // prologue: 3 stages in flight (nChunks >= 3 at every call site)
    issue(0, k0_of(0));
    issue(1, k0_of(1));
    issue(2, k0_of(2));

    for (int ci = 0; ci < nChunks; ci++) {
        if (ci + 3 < nChunks) issue((ci + 3) % NSTAGE, k0_of(ci + 3));
        else asm volatile("cp.async.commit_group;" ::: "memory");
        asm volatile("cp.async.wait_group 3;" ::: "memory");
        __syncthreads();

        uint32_t aB = sBase + (uint32_t)((ci % NSTAGE) * STAGEH) * 2;
        uint32_t bB = aB + BUFH * 2;
        #pragma unroll
        for (int kk = 0; kk < 32; kk += 16) {
            uint32_t afr[2][4];
            #pragma unroll
            for (int mt = 0; mt < 2; mt++) {
                int rowA = warp_m * 32 + mt * 16 + (g & 1) * 8 + r;
                int colA = kk + (g >> 1) * 8;
                uint32_t ad = aB + (uint32_t)(rowA * SSTRIDE + colA) * 2;
                LDMX4(afr[mt][0], afr[mt][1], afr[mt][2], afr[mt][3], ad);
            }
            #pragma unroll
            for (int ntp = 0; ntp < 2; ntp++) {
                int rowB = warp_n * 32 + ntp * 16 + (g >> 1) * 8 + r;
                int colB = kk + (g & 1) * 8;
                uint32_t bd = bB + (uint32_t)(rowB * SSTRIDE + colB) * 2;
                uint32_t b0, b1, b2, b3;
                LDMX4(b0, b1, b2, b3, bd);
                #pragma unroll
                for (int mt = 0; mt < 2; mt++) {
                    MMA16816(acc[mt][2 * ntp], afr[mt], b0, b1);
                    MMA16816(acc[mt][2 * ntp + 1], afr[mt], b2, b3);
                }
            }
        }
    }

    // epilogue
    if (OUTBF16 == 0) {
        float* C = (float*)Cv + coff;
        #pragma unroll
        for (int mt = 0; mt < 2; mt++) {
            int row0 = bm + warp_m * 32 + mt * 16 + (lane >> 2);
            int orow = rowMul ? ((row0 & 1023) + (row0 >> 10) * rowMul) : row0;
            #pragma unroll
            for (int nt = 0; nt < 4; nt++) {
                int col = bn + warp_n * 32 + nt * 8 + (lane & 3) * 2;
                if (col < N) {
                    float* c0 = C + (size_t)orow * ldc + col;
                    *reinterpret_cast<float2*>(c0) =
                        make_float2(acc[mt][nt][0], acc[mt][nt][1]);
                    *reinterpret_cast<float2*>(c0 + 8LL * ldc) =
                        make_float2(acc[mt][nt][2], acc[mt][nt][3]);
                }
            }
        }
    } else {
        __nv_bfloat16* C = (__nv_bfloat16*)Cv + coff;
        #pragma unroll
        for (int mt = 0; mt < 2; mt++) {
            int row0 = bm + warp_m * 32 + mt * 16 + (lane >> 2);
            int orow = rowMul ? ((row0 & 1023) + (row0 >> 10) * rowMul) : row0;
            #pragma unroll
            for (int nt = 0; nt < 4; nt++) {
                int col = bn + warp_n * 32 + nt * 8 + (lane & 3) * 2;
                if (col < N) {
                    #pragma unroll
                    for (int rr = 0; rr < 2; rr++) {
                        __nv_bfloat16 h0, l0, h1, l1;
                        split2(acc[mt][nt][2 * rr + 0], h0, l0);
                        split2(acc[mt][nt][2 * rr + 1], h1, l1);
                        __nv_bfloat162 hp; hp.x = h0; hp.y = h1;
                        __nv_bfloat162 lp; lp.x = l0; lp.y = l1;
                        size_t base = (size_t)(orow + rr * 8) * ldc + col;
                        *reinterpret_cast<__nv_bfloat162*>(C + base) = hp;
                        *reinterpret_cast<__nv_bfloat162*>(C + base + segS) = lp;
                        *reinterpret_cast<__nv_bfloat162*>(C + base + 2 * segS) = hp;
                    }
                }
            }
        }
    }
}

// ---------------- conversions ----------------
// row-major fp32 -> expanded bf16 [rows, 3K]; mode 0 (A): hi|lo|hi, 1 (B): hi|hi|lo
__global__ void convA_kernel(const float* __restrict__ in, __nv_bfloat16* __restrict__ out,
                             long long rows, int K, int ldin, int mode)
{
    long long idx = (long long)blockIdx.x * blockDim.x + threadIdx.x;
    long long total = rows * (long long)K;
    if (idx >= total) return;
    long long r = idx / K;
    int k = (int)(idx - r * K);
    float x = in[r * (long long)ldin + k];
    __nv_bfloat16 hi, lo; split2(x, hi, lo);
    __nv_bfloat16* o = out + r * (3LL * K);
    o[k] = hi;
    o[(long long)K + k] = mode ? hi : lo;
    o[2LL * K + k]      = mode ? lo : hi;
}

// [K,N] row-major -> transposed K-major [N, 3K], hi|hi|lo (B role)
__global__ void convBT_kernel(const float* __restrict__ in, __nv_bfloat16* __restrict__ out,
                              int K, int N, int ldin, long long sIn, long long sOut)
{
    __shared__ float t[32][33];
    int zz = blockIdx.z;
    in  += (long long)zz * sIn;
    out += (long long)zz * sOut;
    int kb = blockIdx.x * 32, nb = blockIdx.y * 32;
    int tx = threadIdx.x, ty = threadIdx.y;   // 32 x 8
    #pragma unroll
    for (int i = 0; i < 32; i += 8)
        t[ty + i][tx] = in[(long long)(kb + ty + i) * ldin + nb + tx];
    __syncthreads();
    long long K3 = 3LL * K;
    #pragma unroll
    for (int i = 0; i < 32; i += 8) {
        int n = nb + ty + i;
        int k = kb + tx;
        float x = t[tx][ty + i];
        __nv_bfloat16 hi, lo; split2(x, hi, lo);
        __nv_bfloat16* o = out + (long long)n * K3;
        o[k] = hi; o[(long long)K + k] = hi; o[2LL * K + k] = lo;
    }
}

// ---------------- RMSNorm -> expanded bf16 (+ optional fp32 copy) ------------
__global__ void rmsnorm_kernel(const float* __restrict__ in, const float* __restrict__ w,
                               float* __restrict__ out32, __nv_bfloat16* __restrict__ out16,
                               int cols, int ldin, int ldout, int ld3, int segS, int role)
{
    long long row = blockIdx.x;
    const float* x = in + row * ldin;
    int tid = threadIdx.x;
    float ss = 0.f;
    for (int c = tid; c < cols; c += 256) { float v = x[c]; ss += v * v; }
    __shared__ float red[256];
    red[tid] = ss; __syncthreads();
    for (int s = 128; s > 0; s >>= 1) {
        if (tid < s) red[tid] += red[tid + s];
        __syncthreads();
    }
    float r = rsqrtf(red[0] / (float)cols + 1e-6f);
    __nv_bfloat16* o = out16 + row * (long long)ld3;
    for (int c = tid; c < cols; c += 256) {
        float v = x[c] * r * w[c];
        if (out32) out32[row * (long long)ldout + c] = v;
        __nv_bfloat16 hi, lo; split2(v, hi, lo);
        o[c] = hi;
        o[segS + c]     = role ? hi : lo;
        o[2 * segS + c] = role ? lo : hi;
    }
}

// keys rope part from g_buf12 cols [2048,2112) -> e_keys (B role)
__global__ void rope_k_kernel(const float* __restrict__ buf12, const int* __restrict__ pos_ids,
                              __nv_bfloat16* __restrict__ ekeys)
{
    int gid = blockIdx.x * blockDim.x + threadIdx.x;
    if (gid >= MM * 32) return;
    int j = gid & 31;
    int row = gid >> 5;
    float pos = (float)pos_ids[row];
    float x0 = buf12[(long long)row * N12 + 2048 + 2 * j];
    float x1 = buf12[(long long)row * N12 + 2048 + 2 * j + 1];
    float o0, o1;
    rope_pair(x0, x1, pos, j, o0, o1);
    long long base = (long long)row * 1728 + KVL;
    store_exp(ekeys, base + j, 576, o0, 1);
    store_exp(ekeys, base + 32 + j, 576, o1, 1);
}

// q rope part -> e_query (A role), row stride 1728, seg 576
__global__ void rope_q_kernel(const float* __restrict__ qpe, const int* __restrict__ pos_ids,
                              __nv_bfloat16* __restrict__ equery)
{
    int gid = blockIdx.x * blockDim.x + threadIdx.x;
    if (gid >= MM * HH * 32) return;
    int j = gid & 31;
    int h = (gid >> 5) & (HH - 1);
    int row = gid >> 10;
    int b = row >> 10;
    int s = row & (SS - 1);
    float pos = (float)pos_ids[row];
    float x0 = qpe[(long long)row * (HH * ROPE) + h * ROPE + 2 * j];
    float x1 = qpe[(long long)row * (HH * ROPE) + h * ROPE + 2 * j + 1];
    float o0, o1;
    rope_pair(x0, x1, pos, j, o0, o1);
    long long base = (((long long)(b * HH + h)) * SS + s) * 1728 + KVL;
    store_exp(equery, base + j, 576, o0, 0);
    store_exp(equery, base + 32 + j, 576, o1, 0);
}

// ---------------- fused causal softmax -> expanded bf16 probs ----------------
__global__ void softmax_kernel(const float* __restrict__ sc, __nv_bfloat16* __restrict__ out)
{
    int i = blockIdx.x;
    int z = blockIdx.y;
    long long base = ((long long)z * SS + i) * SS;
    long long ob = ((long long)z * SS + i) * 3072;
    int tid = threadIdx.x;
    const float scale = 0.07216878364870322f;  // 1/sqrt(192)
    int limit = ((i >> 7) + 1) << 7;           // 128-aligned causal tile limit

    float lm = -1e30f;
    float v[4];
    int cnt = 0;
    for (int j = tid; j <= i; j += 256) {
        v[cnt] = sc[base + j];
        lm = fmaxf(lm, v[cnt]);
        cnt++;
    }
    __shared__ float red[256];
    red[tid] = lm; __syncthreads();
    for (int s = 128; s > 0; s >>= 1) {
        if (tid < s) red[tid] = fmaxf(red[tid], red[tid + s]);
        __syncthreads();
    }
    float m = red[0] * scale;
    __syncthreads();

    float ls = 0.f;
    #pragma unroll
    for (int q = 0; q < 4; q++) {
        if (q < cnt) {
            v[q] = expf(v[q] * scale - m);
            ls += v[q];
        }
    }
    red[tid] = ls; __syncthreads();
    for (int s = 128; s > 0; s >>= 1) {
        if (tid < s) red[tid] += red[tid + s];
        __syncthreads();
    }
    float inv = 1.f / red[0];

    int q = 0;
    for (int j = tid; j < limit; j += 256) {
        float p = (j <= i) ? v[q] * inv : 0.f;
        q++;
        __nv_bfloat16 hi, lo; split2(p, hi, lo);
        out[ob + j] = hi;
        out[ob + 1024 + j] = lo;
        out[ob + 2048 + j] = hi;
    }
}

// ---------------- launch ----------------
static inline int cdiv(long long a, int b) { return (int)((a + b - 1) / b); }

extern "C" void kernel_launch(void* const* d_in, const int* in_sizes, int n_in,
                              void* d_out, int out_size)
{
    const float* hidden    = (const float*)d_in[0];
    const int*   pos       = (const int*)d_in[2];
    const float* w_q_a     = (const float*)d_in[3];
    const float* q_a_ln_w  = (const float*)d_in[4];
    const float* q_rope    = (const float*)d_in[5];
    const float* fusedqk   = (const float*)d_in[6];
    const float* w_kv_a    = (const float*)d_in[7];
    const float* kv_a_ln_w = (const float*)d_in[8];
    const float* v_up      = (const float*)d_in[9];
    const float* w_o       = (const float*)d_in[10];
    float* out = (float*)d_out;

    float *buf12, *bufA, *keys, *scores;
    cudaGetSymbolAddress((void**)&buf12,  g_buf12);
    cudaGetSymbolAddress((void**)&bufA,   g_bufA);
    cudaGetSymbolAddress((void**)&keys,   g_keys);
    cudaGetSymbolAddress((void**)&scores, g_scores);

    __nv_bfloat16 *ehid, *ew12, *eqa, *eqr, *efqk, *equery, *ekeys,
                  *escores, *ekva, *ectx, *evup, *eatt, *ewo;
    cudaGetSymbolAddress((void**)&ehid,    e_hidden);
    cudaGetSymbolAddress((void**)&ew12,    e_w12);
    cudaGetSymbolAddress((void**)&eqa,     e_qa);
    cudaGetSymbolAddress((void**)&eqr,     e_qrope);
    cudaGetSymbolAddress((void**)&efqk,    e_fqk);
    cudaGetSymbolAddress((void**)&equery,  e_query);
    cudaGetSymbolAddress((void**)&ekeys,   e_keys);
    cudaGetSymbolAddress((void**)&escores, e_scores);
    cudaGetSymbolAddress((void**)&ekva,    e_kva);
    cudaGetSymbolAddress((void**)&ectx,    e_ctx);
    cudaGetSymbolAddress((void**)&evup,    e_vup);
    cudaGetSymbolAddress((void**)&eatt,    e_attout);
    cudaGetSymbolAddress((void**)&ewo,     e_wo);

    cudaFuncSetAttribute(mma_gemm<0,0>, cudaFuncAttributeMaxDynamicSharedMemorySize, GSMEM_SZ);
    cudaFuncSetAttribute(mma_gemm<0,1>, cudaFuncAttributeMaxDynamicSharedMemorySize, GSMEM_SZ);
    cudaFuncSetAttribute(mma_gemm<1,0>, cudaFuncAttributeMaxDynamicSharedMemorySize, GSMEM_SZ);
    cudaFuncSetAttribute(mma_gemm<2,1>, cudaFuncAttributeMaxDynamicSharedMemorySize, GSMEM_SZ);

    dim3 tb(32, 8);

    // ---- launches 0-2: conversions needed by the first GEMM ----
    convA_kernel<<<cdiv((long long)2048 * 4096, 256), 256>>>(hidden, ehid, 2048, 4096, 4096, 0);
    convBT_kernel<<<dim3(128, 48, 1), tb>>>(w_q_a,  ew12,  4096, 1536, 1536, 0, 0);
    convBT_kernel<<<dim3(128, 18, 1), tb>>>(w_kv_a, ew12 + (size_t)1536 * 12288,
                                            4096, 576, 576, 0, 0);

    // ---- launch 3 (ncu capture target): [qa_raw | ckv] = hidden @ [w_q_a|w_kv_a] --
    mma_gemm<0, 0><<<dim3(17, 16, 1), 512, GSMEM_SZ>>>(ehid, ew12, buf12,
        2048, N12, 12288, 12288, 12288, N12, 0, 0, 0, 0, 0, 0, 0, 1, 0, 0);

    // ---- rmsnorms + rope_k ----
    rmsnorm_kernel<<<2048, 256>>>(buf12, q_a_ln_w, nullptr, eqa, 1536, N12, 0, 4608, 1536, 0);
    rmsnorm_kernel<<<2048, 256>>>(buf12 + 1536, kv_a_ln_w, keys, ekeys, 512, N12, 512, 1728, 576, 1);
    rope_k_kernel<<<(MM * 32) / 256, 256>>>(buf12, pos, ekeys);

    // ---- kva K-major transpose for ctx GEMM ----
    convBT_kernel<<<dim3(32, 16, 2), tb>>>(keys, ekva, 1024, 512, 512,
        (long long)1024 * 512, (long long)512 * 3072);

    // ---- q_rope weight conversion, then qpe_raw = qa @ q_rope (fp32) ----
    convBT_kernel<<<dim3(48, 64, 1), tb>>>(q_rope, eqr, 1536, 2048, 2048, 0, 0);
    mma_gemm<0, 0><<<dim3(16, 16, 1), 512, GSMEM_SZ>>>(eqa, eqr, bufA,
        2048, 2048, 4608, 4608, 4608, 2048, 0, 0, 0, 0, 0, 0, 0, 1, 0, 0);

    // ---- rope(q) -> e_query rope cols (A role) ----
    rope_q_kernel<<<(MM * HH * 32) / 256, 256>>>(bufA, pos, equery);

    // ---- fusedqk conversion, then q_abs = qa @ fusedqk[h] -> e_query[:512] ----
    convBT_kernel<<<dim3(48, 16, 32), tb>>>(fusedqk, efqk, 1536, 512, 512,
        (long long)1536 * 512, (long long)512 * 4608);
    mma_gemm<0, 1><<<dim3(4, 16, 32), 512, GSMEM_SZ>>>(eqa, efqk, equery,
        2048, 512, 4608, 4608, 4608, 1728, 576,
        0, 0,
        0, (long long)512 * 4608,
        0, (long long)1024 * 1728, 32, 0, 32768);

    // ---- weight conversions for later stages ----
    convBT_kernel<<<dim3(16, 4, 32),   tb>>>(v_up, evup, 512, 128, 128,
        (long long)512 * 128, (long long)128 * 1536);
    convBT_kernel<<<dim3(128, 128, 1), tb>>>(w_o, ewo, 4096, 4096, 4096, 0, 0);

    // ---- scores = query @ keys^T (fp32, causal tile skip) ----
    mma_gemm<1, 0><<<dim3(8, 8, 64), 512, GSMEM_SZ>>>(equery, ekeys, scores,
        1024, 1024, 1728, 1728, 1728, 1024, 0,
        (long long)32 * 1024 * 1728, (long long)1024 * 1728,
        (long long)1024 * 1728, 0,
        (long long)32 * 1024 * 1024, (long long)1024 * 1024, 32, 0, 0);

    // ---- fused softmax -> e_scores (A role, 128-aligned zero fill) ----
    softmax_kernel<<<dim3(1024, 64), 256>>>(scores, escores);

    // ---- ctx = probs @ kva -> e_ctx (bf16 epilogue, chunk skip) ----
    mma_gemm<2, 1><<<dim3(4, 8, 64), 512, GSMEM_SZ>>>(escores, ekva, ectx,
        1024, 512, 3072, 3072, 3072, 1536, 512,
        (long long)32 * 1024 * 3072, (long long)1024 * 3072,
        (long long)512 * 3072, 0,
        (long long)32 * 1024 * 1536, (long long)1024 * 1536, 32, 1023, 0);

    // ---- attout = ctx @ v_up[h] -> e_attout (bf16 epilogue) ----
    mma_gemm<0, 1><<<dim3(1, 8, 64), 512, GSMEM_SZ>>>(ectx, evup, eatt,
        1024, 128, 1536, 1536, 1536, 12288, 4096,
        (long long)32 * 1024 * 1536, (long long)1024 * 1536,
        0, (long long)128 * 1536,
        (long long)1024 * 12288, 128, 32, 0, 0);

    // ---- out = attout @ w_o (fp32) ----
    mma_gemm<0, 0><<<dim3(32, 16, 1), 512, GSMEM_SZ>>>(eatt, ewo, out,
        2048, 4096, 12288, 12288, 12288, 4096, 0, 0, 0, 0, 0, 0, 0, 1, 0, 0);
}

// round 14
// speedup vs baseline: 1.2028x; 1.2028x over previous
#include <cuda_runtime.h>
#include <cuda_bf16.h>
#include <cstdint>

#define BB 2
#define SS 1024
#define HID 4096
#define HH 32
#define QL 1536
#define KVL 512
#define ROPE 64
#define DD 576              // KVL + ROPE
#define MM (BB*SS)          // 2048
#define N12 2112            // QL + DD (merged proj width)

// ---------------- fp32 scratch ----------------
__device__ __align__(16) float g_buf12[(size_t)MM * N12];   // [qa_raw | ckv]
__device__ __align__(16) float g_bufA[(size_t)MM * 2048];   // qpe_raw
__device__ __align__(16) float g_keys[(size_t)MM * KVL];    // kva fp32 (for ekva transpose)
__device__ __align__(16) float g_scores[(size_t)64 * SS * SS];

// ---------------- bf16 expanded operands (x3 along K for hi/lo split) --------
__device__ __align__(1024) __nv_bfloat16 e_hidden[(size_t)2048 * 12288];
__device__ __align__(1024) __nv_bfloat16 e_w12  [(size_t)N12 * 12288];   // [wqa rows | wkva rows]
__device__ __align__(1024) __nv_bfloat16 e_qa   [(size_t)2048 * 4608];
__device__ __align__(1024) __nv_bfloat16 e_qrope[(size_t)2048 * 4608];
__device__ __align__(1024) __nv_bfloat16 e_fqk  [(size_t)32 * 512 * 4608];
__device__ __align__(1024) __nv_bfloat16 e_query[(size_t)65536 * 1728];
__device__ __align__(1024) __nv_bfloat16 e_keys [(size_t)2048 * 1728];
__device__ __align__(1024) __nv_bfloat16 e_scores[(size_t)65536 * 3072];
__device__ __align__(1024) __nv_bfloat16 e_kva  [(size_t)2 * 512 * 3072];
__device__ __align__(1024) __nv_bfloat16 e_ctx  [(size_t)65536 * 1536];
__device__ __align__(1024) __nv_bfloat16 e_vup  [(size_t)32 * 128 * 1536];
__device__ __align__(1024) __nv_bfloat16 e_attout[(size_t)2048 * 12288];
__device__ __align__(1024) __nv_bfloat16 e_wo   [(size_t)4096 * 12288];

// ---------------- helpers ----------------
__device__ __forceinline__ uint32_t smem_u32(const void* p) {
    uint32_t a;
    asm("{ .reg .u64 t; cvta.to.shared.u64 t, %1; cvt.u32.u64 %0, t; }" : "=r"(a) : "l"(p));
    return a;
}
__device__ __forceinline__ void split2(float x, __nv_bfloat16& hi, __nv_bfloat16& lo) {
    hi = __float2bfloat16(x);
    lo = __float2bfloat16(x - __bfloat162float(hi));
}
__device__ __forceinline__ void rope_pair(float x0, float x1, float pos, int j,
                                          float& o0, float& o1)
{
    float inv = expf(-(float)j * 0.28782313662425581f);  // ln(10000)/32
    float f = pos * inv;
    float c = cosf(f), s = sinf(f);
    o0 = x0 * c - x1 * s;
    o1 = x1 * c + x0 * s;
}
__device__ __forceinline__ void store_exp(__nv_bfloat16* o, long long idx, int segS,
                                          float v, int role)
{
    __nv_bfloat16 hi, lo; split2(v, hi, lo);
    o[idx] = hi;
    o[idx + segS]     = role ? hi : lo;
    o[idx + 2 * segS] = role ? lo : hi;
}

#define LDMX4(d0,d1,d2,d3,addr) \
    asm volatile("ldmatrix.sync.aligned.m8n8.x4.shared.b16 {%0,%1,%2,%3}, [%4];" \
        : "=r"(d0), "=r"(d1), "=r"(d2), "=r"(d3) : "r"(addr))

#define MMA16816(c, a, b0, b1) \
    asm volatile("mma.sync.aligned.m16n8k16.row.col.f32.bf16.bf16.f32 " \
        "{%0,%1,%2,%3}, {%4,%5,%6,%7}, {%8,%9}, {%0,%1,%2,%3};" \
        : "+f"((c)[0]), "+f"((c)[1]), "+f"((c)[2]), "+f"((c)[3]) \
        : "r"((a)[0]), "r"((a)[1]), "r"((a)[2]), "r"((a)[3]), "r"(b0), "r"(b1))

// ---------------- HMMA bf16 GEMM: C[M,N] = A[M,K] @ B[N,K]^T (both K-major) --
// 128x128 CTA, BK=64, 256 thr, 8 warps (4x2), warp tile 32x64, 2 CTAs/SM.
// 3-stage cp.async ring of 64-K chunks; ONE sync + ONE wait per 64 K.
// Ring: prologue issue(0,1); iter ci: wait(1), sync, compute(ci), issue(ci+2).
//   issue targets stage (ci-1)%3 whose readers all passed sync(ci). Safe.
// Requires nChunks >= 2 (min at call sites: 6).
// OUTBF16=0: fp32 C. OUTBF16=1: bf16 3-term A-role hi|lo|hi at +{0,segS,2segS}.
// CAUSAL: 0 none; 1 skip bx>by; 2 token-chunk skip (kLimit=(by+1)*128).
// rowMul!=0: epilogue row remap orow = (row & 1023) + (row >> 10) * rowMul.
#define SSTRIDE 72                  // halves per 64-col row (144B = 9 x 16B, odd -> conflict-free)
#define BUFH (128 * SSTRIDE)        // halves per operand per stage
#define STAGEH (2 * BUFH)           // A + B per stage
#define NSTAGE 3
#define GSMEM_SZ (NSTAGE * STAGEH * 2)   // 110592 bytes

template<int CAUSAL, int OUTBF16>
__global__ __launch_bounds__(256, 2)
void mma_gemm(const __nv_bfloat16* __restrict__ A,
              const __nv_bfloat16* __restrict__ B,
              void* __restrict__ Cv,
              int M, int N, int K, int lda, int ldb, int ldc, int segS,
              long long sAo, long long sAi, long long sBo, long long sBi,
              long long sCo, long long sCi, int innerCnt, int tokMask, int rowMul)
{
    if (CAUSAL == 1 && blockIdx.x > blockIdx.y) return;

    extern __shared__ __align__(16) char dsm[];

    int z = blockIdx.z;
    int outer = z / innerCnt, inner = z - outer * innerCnt;
    A += outer * sAo + inner * sAi;
    B += outer * sBo + inner * sBi;
    long long coff = outer * sCo + inner * sCi;

    int tid = threadIdx.x, lane = tid & 31, wid = tid >> 5;
    int warp_m = wid & 3, warp_n = wid >> 2;
    int bm = blockIdx.y * 128, bn = blockIdx.x * 128;

    uint32_t sBase = smem_u32(dsm);

    int per = 0, nChunks;
    int seg = tokMask + 1;
    if (CAUSAL == 2) {
        int kl = (blockIdx.y + 1) * 128;
        if (kl > seg) kl = seg;
        per = kl >> 6;
        nChunks = (K / seg) * per;
    } else {
        nChunks = K >> 6;
    }

    auto k0_of = [&](int ci) -> int {
        if (CAUSAL == 2) return (ci / per) * seg + (ci % per) * 64;
        return ci * 64;
    };

    auto issue = [&](int stage, int k0) {
        uint32_t aB = sBase + (uint32_t)(stage * STAGEH) * 2;
        uint32_t bB = aB + BUFH * 2;
        #pragma unroll
        for (int u = tid; u < 1024; u += 256) {
            int row = u >> 3, c = u & 7;
            const __nv_bfloat16* src = A + (size_t)(bm + row) * lda + k0 + c * 8;
            uint32_t dst = aB + (uint32_t)(row * SSTRIDE + c * 8) * 2;
            asm volatile("cp.async.cg.shared.global [%0], [%1], 16;"
                         :: "r"(dst), "l"(src));
        }
        #pragma unroll
        for (int u = tid; u < 1024; u += 256) {
            int row = u >> 3, c = u & 7;
            int ok = (bn + row) < N;
            const __nv_bfloat16* src = B + (size_t)(bn + (ok ? row : 0)) * ldb + k0 + c * 8;
            uint32_t dst = bB + (uint32_t)(row * SSTRIDE + c * 8) * 2;
            int sz = ok ? 16 : 0;
            asm volatile("cp.async.cg.shared.global [%0], [%1], 16, %2;"
                         :: "r"(dst), "l"(src), "r"(sz));
        }
        asm volatile("cp.async.commit_group;" ::: "memory");
    };

    float acc[2][8][4];
    #pragma unroll
    for (int i = 0; i < 2; i++)
        #pragma unroll
        for (int j = 0; j < 8; j++)
            #pragma unroll
            for (int q = 0; q < 4; q++) acc[i][j][q] = 0.f;

    int g = lane >> 3, r = lane & 7;

    // prologue: 2 stages in flight (nChunks >= 2 at every call site)
    issue(0, k0_of(0));
    issue(1, k0_of(1));

    for (int ci = 0; ci < nChunks; ci++) {
        asm volatile("cp.async.wait_group 1;" ::: "memory");
        __syncthreads();

        uint32_t aB = sBase + (uint32_t)((ci % NSTAGE) * STAGEH) * 2;
        uint32_t bB = aB + BUFH * 2;
        #pragma unroll
        for (int kk = 0; kk < 64; kk += 16) {
            uint32_t afr[2][4];
            #pragma unroll
            for (int mt = 0; mt < 2; mt++) {
                int rowA = warp_m * 32 + mt * 16 + (g & 1) * 8 + r;
                int colA = kk + (g >> 1) * 8;
                uint32_t ad = aB + (uint32_t)(rowA * SSTRIDE + colA) * 2;
                LDMX4(afr[mt][0], afr[mt][1], afr[mt][2], afr[mt][3], ad);
            }
            #pragma unroll
            for (int ntp = 0; ntp < 4; ntp++) {
                int rowB = warp_n * 64 + ntp * 16 + (g >> 1) * 8 + r;
                int colB = kk + (g & 1) * 8;
                uint32_t bd = bB + (uint32_t)(rowB * SSTRIDE + colB) * 2;
                uint32_t b0, b1, b2, b3;
                LDMX4(b0, b1, b2, b3, bd);
                #pragma unroll
                for (int mt = 0; mt < 2; mt++) {
                    MMA16816(acc[mt][2 * ntp], afr[mt], b0, b1);
                    MMA16816(acc[mt][2 * ntp + 1], afr[mt], b2, b3);
                }
            }
        }

        // refill the stage just freed (stage (ci-1)%3 == (ci+2)%3); all readers
        // of it passed the sync above, so overwrite is safe.
        if (ci + 2 < nChunks) issue((ci + 2) % NSTAGE, k0_of(ci + 2));
        else asm volatile("cp.async.commit_group;" ::: "memory");
    }

    // epilogue
    if (OUTBF16 == 0) {
        float* C = (float*)Cv + coff;
        #pragma unroll
        for (int mt = 0; mt < 2; mt++) {
            int row0 = bm + warp_m * 32 + mt * 16 + (lane >> 2);
            int orow = rowMul ? ((row0 & 1023) + (row0 >> 10) * rowMul) : row0;
            #pragma unroll
            for (int nt = 0; nt < 8; nt++) {
                int col = bn + warp_n * 64 + nt * 8 + (lane & 3) * 2;
                if (col < N) {
                    float* c0 = C + (size_t)orow * ldc + col;
                    *reinterpret_cast<float2*>(c0) =
                        make_float2(acc[mt][nt][0], acc[mt][nt][1]);
                    *reinterpret_cast<float2*>(c0 + 8LL * ldc) =
                        make_float2(acc[mt][nt][2], acc[mt][nt][3]);
                }
            }
        }
    } else {
        __nv_bfloat16* C = (__nv_bfloat16*)Cv + coff;
        #pragma unroll
        for (int mt = 0; mt < 2; mt++) {
            int row0 = bm + warp_m * 32 + mt * 16 + (lane >> 2);
            int orow = rowMul ? ((row0 & 1023) + (row0 >> 10) * rowMul) : row0;
            #pragma unroll
            for (int nt = 0; nt < 8; nt++) {
                int col = bn + warp_n * 64 + nt * 8 + (lane & 3) * 2;
                if (col < N) {
                    #pragma unroll
                    for (int rr = 0; rr < 2; rr++) {
                        __nv_bfloat16 h0, l0, h1, l1;
                        split2(acc[mt][nt][2 * rr + 0], h0, l0);
                        split2(acc[mt][nt][2 * rr + 1], h1, l1);
                        __nv_bfloat162 hp; hp.x = h0; hp.y = h1;
                        __nv_bfloat162 lp; lp.x = l0; lp.y = l1;
                        size_t base = (size_t)(orow + rr * 8) * ldc + col;
                        *reinterpret_cast<__nv_bfloat162*>(C + base) = hp;
                        *reinterpret_cast<__nv_bfloat162*>(C + base + segS) = lp;
                        *reinterpret_cast<__nv_bfloat162*>(C + base + 2 * segS) = hp;
                    }
                }
            }
        }
    }
}

// ---------------- conversions ----------------
// row-major fp32 -> expanded bf16 [rows, 3K]; mode 0 (A): hi|lo|hi, 1 (B): hi|hi|lo
__global__ void convA_kernel(const float* __restrict__ in, __nv_bfloat16* __restrict__ out,
                             long long rows, int K, int ldin, int mode)
{
    long long idx = (long long)blockIdx.x * blockDim.x + threadIdx.x;
    long long total = rows * (long long)K;
    if (idx >= total) return;
    long long r = idx / K;
    int k = (int)(idx - r * K);
    float x = in[r * (long long)ldin + k];
    __nv_bfloat16 hi, lo; split2(x, hi, lo);
    __nv_bfloat16* o = out + r * (3LL * K);
    o[k] = hi;
    o[(long long)K + k] = mode ? hi : lo;
    o[2LL * K + k]      = mode ? lo : hi;
}

// [K,N] row-major -> transposed K-major [N, 3K], hi|hi|lo (B role)
__global__ void convBT_kernel(const float* __restrict__ in, __nv_bfloat16* __restrict__ out,
                              int K, int N, int ldin, long long sIn, long long sOut)
{
    __shared__ float t[32][33];
    int zz = blockIdx.z;
    in  += (long long)zz * sIn;
    out += (long long)zz * sOut;
    int kb = blockIdx.x * 32, nb = blockIdx.y * 32;
    int tx = threadIdx.x, ty = threadIdx.y;   // 32 x 8
    #pragma unroll
    for (int i = 0; i < 32; i += 8)
        t[ty + i][tx] = in[(long long)(kb + ty + i) * ldin + nb + tx];
    __syncthreads();
    long long K3 = 3LL * K;
    #pragma unroll
    for (int i = 0; i < 32; i += 8) {
        int n = nb + ty + i;
        int k = kb + tx;
        float x = t[tx][ty + i];
        __nv_bfloat16 hi, lo; split2(x, hi, lo);
        __nv_bfloat16* o = out + (long long)n * K3;
        o[k] = hi; o[(long long)K + k] = hi; o[2LL * K + k] = lo;
    }
}

// ---------------- RMSNorm -> expanded bf16 (+ optional fp32 copy) ------------
__global__ void rmsnorm_kernel(const float* __restrict__ in, const float* __restrict__ w,
                               float* __restrict__ out32, __nv_bfloat16* __restrict__ out16,
                               int cols, int ldin, int ldout, int ld3, int segS, int role)
{
    long long row = blockIdx.x;
    const float* x = in + row * ldin;
    int tid = threadIdx.x;
    float ss = 0.f;
    for (int c = tid; c < cols; c += 256) { float v = x[c]; ss += v * v; }
    __shared__ float red[256];
    red[tid] = ss; __syncthreads();
    for (int s = 128; s > 0; s >>= 1) {
        if (tid < s) red[tid] += red[tid + s];
        __syncthreads();
    }
    float r = rsqrtf(red[0] / (float)cols + 1e-6f);
    __nv_bfloat16* o = out16 + row * (long long)ld3;
    for (int c = tid; c < cols; c += 256) {
        float v = x[c] * r * w[c];
        if (out32) out32[row * (long long)ldout + c] = v;
        __nv_bfloat16 hi, lo; split2(v, hi, lo);
        o[c] = hi;
        o[segS + c]     = role ? hi : lo;
        o[2 * segS + c] = role ? lo : hi;
    }
}

// keys rope part from g_buf12 cols [2048,2112) -> e_keys (B role)
__global__ void rope_k_kernel(const float* __restrict__ buf12, const int* __restrict__ pos_ids,
                              __nv_bfloat16* __restrict__ ekeys)
{
    int gid = blockIdx.x * blockDim.x + threadIdx.x;
    if (gid >= MM * 32) return;
    int j = gid & 31;
    int row = gid >> 5;
    float pos = (float)pos_ids[row];
    float x0 = buf12[(long long)row * N12 + 2048 + 2 * j];
    float x1 = buf12[(long long)row * N12 + 2048 + 2 * j + 1];
    float o0, o1;
    rope_pair(x0, x1, pos, j, o0, o1);
    long long base = (long long)row * 1728 + KVL;
    store_exp(ekeys, base + j, 576, o0, 1);
    store_exp(ekeys, base + 32 + j, 576, o1, 1);
}

// q rope part -> e_query (A role), row stride 1728, seg 576
__global__ void rope_q_kernel(const float* __restrict__ qpe, const int* __restrict__ pos_ids,
                              __nv_bfloat16* __restrict__ equery)
{
    int gid = blockIdx.x * blockDim.x + threadIdx.x;
    if (gid >= MM * HH * 32) return;
    int j = gid & 31;
    int h = (gid >> 5) & (HH - 1);
    int row = gid >> 10;
    int b = row >> 10;
    int s = row & (SS - 1);
    float pos = (float)pos_ids[row];
    float x0 = qpe[(long long)row * (HH * ROPE) + h * ROPE + 2 * j];
    float x1 = qpe[(long long)row * (HH * ROPE) + h * ROPE + 2 * j + 1];
    float o0, o1;
    rope_pair(x0, x1, pos, j, o0, o1);
    long long base = (((long long)(b * HH + h)) * SS + s) * 1728 + KVL;
    store_exp(equery, base + j, 576, o0, 0);
    store_exp(equery, base + 32 + j, 576, o1, 0);
}

// ---------------- fused causal softmax -> expanded bf16 probs ----------------
__global__ void softmax_kernel(const float* __restrict__ sc, __nv_bfloat16* __restrict__ out)
{
    int i = blockIdx.x;
    int z = blockIdx.y;
    long long base = ((long long)z * SS + i) * SS;
    long long ob = ((long long)z * SS + i) * 3072;
    int tid = threadIdx.x;
    const float scale = 0.07216878364870322f;  // 1/sqrt(192)
    int limit = ((i >> 7) + 1) << 7;           // 128-aligned causal tile limit

    float lm = -1e30f;
    float v[4];
    int cnt = 0;
    for (int j = tid; j <= i; j += 256) {
        v[cnt] = sc[base + j];
        lm = fmaxf(lm, v[cnt]);
        cnt++;
    }
    __shared__ float red[256];
    red[tid] = lm; __syncthreads();
    for (int s = 128; s > 0; s >>= 1) {
        if (tid < s) red[tid] = fmaxf(red[tid], red[tid + s]);
        __syncthreads();
    }
    float m = red[0] * scale;
    __syncthreads();

    float ls = 0.f;
    #pragma unroll
    for (int q = 0; q < 4; q++) {
        if (q < cnt) {
            v[q] = expf(v[q] * scale - m);
            ls += v[q];
        }
    }
    red[tid] = ls; __syncthreads();
    for (int s = 128; s > 0; s >>= 1) {
        if (tid < s) red[tid] += red[tid + s];
        __syncthreads();
    }
    float inv = 1.f / red[0];

    int q = 0;
    for (int j = tid; j < limit; j += 256) {
        float p = (j <= i) ? v[q] * inv : 0.f;
        q++;
        __nv_bfloat16 hi, lo; split2(p, hi, lo);
        out[ob + j] = hi;
        out[ob + 1024 + j] = lo;
        out[ob + 2048 + j] = hi;
    }
}

// ---------------- launch ----------------
static inline int cdiv(long long a, int b) { return (int)((a + b - 1) / b); }

extern "C" void kernel_launch(void* const* d_in, const int* in_sizes, int n_in,
                              void* d_out, int out_size)
{
    const float* hidden    = (const float*)d_in[0];
    const int*   pos       = (const int*)d_in[2];
    const float* w_q_a     = (const float*)d_in[3];
    const float* q_a_ln_w  = (const float*)d_in[4];
    const float* q_rope    = (const float*)d_in[5];
    const float* fusedqk   = (const float*)d_in[6];
    const float* w_kv_a    = (const float*)d_in[7];
    const float* kv_a_ln_w = (const float*)d_in[8];
    const float* v_up      = (const float*)d_in[9];
    const float* w_o       = (const float*)d_in[10];
    float* out = (float*)d_out;

    float *buf12, *bufA, *keys, *scores;
    cudaGetSymbolAddress((void**)&buf12,  g_buf12);
    cudaGetSymbolAddress((void**)&bufA,   g_bufA);
    cudaGetSymbolAddress((void**)&keys,   g_keys);
    cudaGetSymbolAddress((void**)&scores, g_scores);

    __nv_bfloat16 *ehid, *ew12, *eqa, *eqr, *efqk, *equery, *ekeys,
                  *escores, *ekva, *ectx, *evup, *eatt, *ewo;
    cudaGetSymbolAddress((void**)&ehid,    e_hidden);
    cudaGetSymbolAddress((void**)&ew12,    e_w12);
    cudaGetSymbolAddress((void**)&eqa,     e_qa);
    cudaGetSymbolAddress((void**)&eqr,     e_qrope);
    cudaGetSymbolAddress((void**)&efqk,    e_fqk);
    cudaGetSymbolAddress((void**)&equery,  e_query);
    cudaGetSymbolAddress((void**)&ekeys,   e_keys);
    cudaGetSymbolAddress((void**)&escores, e_scores);
    cudaGetSymbolAddress((void**)&ekva,    e_kva);
    cudaGetSymbolAddress((void**)&ectx,    e_ctx);
    cudaGetSymbolAddress((void**)&evup,    e_vup);
    cudaGetSymbolAddress((void**)&eatt,    e_attout);
    cudaGetSymbolAddress((void**)&ewo,     e_wo);

    cudaFuncSetAttribute(mma_gemm<0,0>, cudaFuncAttributeMaxDynamicSharedMemorySize, GSMEM_SZ);
    cudaFuncSetAttribute(mma_gemm<0,1>, cudaFuncAttributeMaxDynamicSharedMemorySize, GSMEM_SZ);
    cudaFuncSetAttribute(mma_gemm<1,0>, cudaFuncAttributeMaxDynamicSharedMemorySize, GSMEM_SZ);
    cudaFuncSetAttribute(mma_gemm<2,1>, cudaFuncAttributeMaxDynamicSharedMemorySize, GSMEM_SZ);

    dim3 tb(32, 8);

    // ---- launches 0-2: conversions needed by the first GEMM ----
    convA_kernel<<<cdiv((long long)2048 * 4096, 256), 256>>>(hidden, ehid, 2048, 4096, 4096, 0);
    convBT_kernel<<<dim3(128, 48, 1), tb>>>(w_q_a,  ew12,  4096, 1536, 1536, 0, 0);
    convBT_kernel<<<dim3(128, 18, 1), tb>>>(w_kv_a, ew12 + (size_t)1536 * 12288,
                                            4096, 576, 576, 0, 0);

    // ---- launch 3 (ncu capture target): [qa_raw | ckv] = hidden @ [w_q_a|w_kv_a] --
    mma_gemm<0, 0><<<dim3(17, 16, 1), 256, GSMEM_SZ>>>(ehid, ew12, buf12,
        2048, N12, 12288, 12288, 12288, N12, 0, 0, 0, 0, 0, 0, 0, 1, 0, 0);

    // ---- rmsnorms + rope_k ----
    rmsnorm_kernel<<<2048, 256>>>(buf12, q_a_ln_w, nullptr, eqa, 1536, N12, 0, 4608, 1536, 0);
    rmsnorm_kernel<<<2048, 256>>>(buf12 + 1536, kv_a_ln_w, keys, ekeys, 512, N12, 512, 1728, 576, 1);
    rope_k_kernel<<<(MM * 32) / 256, 256>>>(buf12, pos, ekeys);

    // ---- kva K-major transpose for ctx GEMM ----
    convBT_kernel<<<dim3(32, 16, 2), tb>>>(keys, ekva, 1024, 512, 512,
        (long long)1024 * 512, (long long)512 * 3072);

    // ---- q_rope weight conversion, then qpe_raw = qa @ q_rope (fp32) ----
    convBT_kernel<<<dim3(48, 64, 1), tb>>>(q_rope, eqr, 1536, 2048, 2048, 0, 0);
    mma_gemm<0, 0><<<dim3(16, 16, 1), 256, GSMEM_SZ>>>(eqa, eqr, bufA,
        2048, 2048, 4608, 4608, 4608, 2048, 0, 0, 0, 0, 0, 0, 0, 1, 0, 0);

    // ---- rope(q) -> e_query rope cols (A role) ----
    rope_q_kernel<<<(MM * HH * 32) / 256, 256>>>(bufA, pos, equery);

    // ---- fusedqk conversion, then q_abs = qa @ fusedqk[h] -> e_query[:512] ----
    convBT_kernel<<<dim3(48, 16, 32), tb>>>(fusedqk, efqk, 1536, 512, 512,
        (long long)1536 * 512, (long long)512 * 4608);
    mma_gemm<0, 1><<<dim3(4, 16, 32), 256, GSMEM_SZ>>>(eqa, efqk, equery,
        2048, 512, 4608, 4608, 4608, 1728, 576,
        0, 0,
        0, (long long)512 * 4608,
        0, (long long)1024 * 1728, 32, 0, 32768);

    // ---- weight conversions for later stages ----
    convBT_kernel<<<dim3(16, 4, 32),   tb>>>(v_up, evup, 512, 128, 128,
        (long long)512 * 128, (long long)128 * 1536);
    convBT_kernel<<<dim3(128, 128, 1), tb>>>(w_o, ewo, 4096, 4096, 4096, 0, 0);

    // ---- scores = query @ keys^T (fp32, causal tile skip) ----
    mma_gemm<1, 0><<<dim3(8, 8, 64), 256, GSMEM_SZ>>>(equery, ekeys, scores,
        1024, 1024, 1728, 1728, 1728, 1024, 0,
        (long long)32 * 1024 * 1728, (long long)1024 * 1728,
        (long long)1024 * 1728, 0,
        (long long)32 * 1024 * 1024, (long long)1024 * 1024, 32, 0, 0);

    // ---- fused softmax -> e_scores (A role, 128-aligned zero fill) ----
    softmax_kernel<<<dim3(1024, 64), 256>>>(scores, escores);

    // ---- ctx = probs @ kva -> e_ctx (bf16 epilogue, chunk skip) ----
    mma_gemm<2, 1><<<dim3(4, 8, 64), 256, GSMEM_SZ>>>(escores, ekva, ectx,
        1024, 512, 3072, 3072, 3072, 1536, 512,
        (long long)32 * 1024 * 3072, (long long)1024 * 3072,
        (long long)512 * 3072, 0,
        (long long)32 * 1024 * 1536, (long long)1024 * 1536, 32, 1023, 0);

    // ---- attout = ctx @ v_up[h] -> e_attout (bf16 epilogue) ----
    mma_gemm<0, 1><<<dim3(1, 8, 64), 256, GSMEM_SZ>>>(ectx, evup, eatt,
        1024, 128, 1536, 1536, 1536, 12288, 4096,
        (long long)32 * 1024 * 1536, (long long)1024 * 1536,
        0, (long long)128 * 1536,
        (long long)1024 * 12288, 128, 32, 0, 0);

    // ---- out = attout @ w_o (fp32) ----
    mma_gemm<0, 0><<<dim3(32, 16, 1), 256, GSMEM_SZ>>>(eatt, ewo, out,
        2048, 4096, 12288, 12288, 12288, 4096, 0, 0, 0, 0, 0, 0, 0, 1, 0, 0);
}

// round 15
// speedup vs baseline: 1.2070x; 1.0035x over previous
#include <cuda_runtime.h>
#include <cuda_bf16.h>
#include <cstdint>

#define BB 2
#define SS 1024
#define HID 4096
#define HH 32
#define QL 1536
#define KVL 512
#define ROPE 64
#define DD 576              // KVL + ROPE
#define MM (BB*SS)          // 2048
#define N12 2112            // QL + DD (merged proj width)

// ---------------- fp32 scratch ----------------
__device__ __align__(16) float g_buf12[(size_t)MM * N12];   // [qa_raw | ckv]
__device__ __align__(16) float g_bufA[(size_t)MM * 2048];   // qpe_raw
__device__ __align__(16) float g_keys[(size_t)MM * KVL];    // kva fp32 (for ekva transpose)
__device__ __align__(16) float g_scores[(size_t)64 * SS * SS];

// ------------- bf16 expanded operands, dedup [hi|lo] (K maps via wrap) -------
__device__ __align__(1024) __nv_bfloat16 e_hidden[(size_t)2048 * 8192];
__device__ __align__(1024) __nv_bfloat16 e_w12  [(size_t)N12 * 8192];
__device__ __align__(1024) __nv_bfloat16 e_qa   [(size_t)2048 * 3072];
__device__ __align__(1024) __nv_bfloat16 e_qrope[(size_t)2048 * 3072];
__device__ __align__(1024) __nv_bfloat16 e_fqk  [(size_t)32 * 512 * 3072];
__device__ __align__(1024) __nv_bfloat16 e_query[(size_t)65536 * 1152];
__device__ __align__(1024) __nv_bfloat16 e_keys [(size_t)2048 * 1152];
__device__ __align__(1024) __nv_bfloat16 e_scores[(size_t)65536 * 2048];
__device__ __align__(1024) __nv_bfloat16 e_kva  [(size_t)2 * 512 * 2048];
__device__ __align__(1024) __nv_bfloat16 e_ctx  [(size_t)65536 * 1024];
__device__ __align__(1024) __nv_bfloat16 e_vup  [(size_t)32 * 128 * 1024];
__device__ __align__(1024) __nv_bfloat16 e_attout[(size_t)2048 * 8192];
__device__ __align__(1024) __nv_bfloat16 e_wo   [(size_t)4096 * 8192];

// ---------------- helpers ----------------
__device__ __forceinline__ uint32_t smem_u32(const void* p) {
    uint32_t a;
    asm("{ .reg .u64 t; cvta.to.shared.u64 t, %1; cvt.u32.u64 %0, t; }" : "=r"(a) : "l"(p));
    return a;
}
__device__ __forceinline__ void split2(float x, __nv_bfloat16& hi, __nv_bfloat16& lo) {
    hi = __float2bfloat16(x);
    lo = __float2bfloat16(x - __bfloat162float(hi));
}
__device__ __forceinline__ void rope_pair(float x0, float x1, float pos, int j,
                                          float& o0, float& o1)
{
    float inv = expf(-(float)j * 0.28782313662425581f);  // ln(10000)/32
    float f = pos * inv;
    float c = cosf(f), s = sinf(f);
    o0 = x0 * c - x1 * s;
    o1 = x1 * c + x0 * s;
}
__device__ __forceinline__ void store_exp(__nv_bfloat16* o, long long idx, int segS, float v)
{
    __nv_bfloat16 hi, lo; split2(v, hi, lo);
    o[idx] = hi;
    o[idx + segS] = lo;
}

#define LDMX4(d0,d1,d2,d3,addr) \
    asm volatile("ldmatrix.sync.aligned.m8n8.x4.shared.b16 {%0,%1,%2,%3}, [%4];" \
        : "=r"(d0), "=r"(d1), "=r"(d2), "=r"(d3) : "r"(addr))

#define MMA16816(c, a, b0, b1) \
    asm volatile("mma.sync.aligned.m16n8k16.row.col.f32.bf16.bf16.f32 " \
        "{%0,%1,%2,%3}, {%4,%5,%6,%7}, {%8,%9}, {%0,%1,%2,%3};" \
        : "+f"((c)[0]), "+f"((c)[1]), "+f"((c)[2]), "+f"((c)[3]) \
        : "r"((a)[0]), "r"((a)[1]), "r"((a)[2]), "r"((a)[3]), "r"(b0), "r"(b1))

// ---------------- HMMA bf16 GEMM: C[M,N] = A[M,K] @ B[N,K]^T ----------------
// Logical K = 3*segK (hi|lo|hi on A, hi|hi|lo on B); storage is dedup [hi|lo]
// of width 2*segK. Fill wraps: kA = k0<2segK ? k0 : k0-2segK;
//                              kB = k0<segK  ? k0 : k0-segK.
// 128x128 CTA, BK=64, 256 thr, 8 warps (4x2), warp tile 32x64, 2 CTAs/SM.
// 3-stage ring of 64-K chunks, ONE sync + ONE wait per chunk.
// OUTBF16=0: fp32 C. OUTBF16=1: dedup bf16 out: hi at col, lo at col+segS.
// CAUSAL: 0 none; 1 skip bx>by; 2 token-chunk skip (kLimit=(by+1)*128).
// rowMul!=0: epilogue row remap orow = (row & 1023) + (row >> 10) * rowMul.
#define SSTRIDE 72                  // halves per 64-col row (144B, conflict-free)
#define BUFH (128 * SSTRIDE)
#define STAGEH (2 * BUFH)
#define NSTAGE 3
#define GSMEM_SZ (NSTAGE * STAGEH * 2)   // 110592 bytes

template<int CAUSAL, int OUTBF16>
__global__ __launch_bounds__(256, 2)
void mma_gemm(const __nv_bfloat16* __restrict__ A,
              const __nv_bfloat16* __restrict__ B,
              void* __restrict__ Cv,
              int M, int N, int K, int lda, int ldb, int ldc, int segS, int segK,
              long long sAo, long long sAi, long long sBo, long long sBi,
              long long sCo, long long sCi, int innerCnt, int tokMask, int rowMul)
{
    if (CAUSAL == 1 && blockIdx.x > blockIdx.y) return;

    extern __shared__ __align__(16) char dsm[];

    int z = blockIdx.z;
    int outer = z / innerCnt, inner = z - outer * innerCnt;
    A += outer * sAo + inner * sAi;
    B += outer * sBo + inner * sBi;
    long long coff = outer * sCo + inner * sCi;

    int tid = threadIdx.x, lane = tid & 31, wid = tid >> 5;
    int warp_m = wid & 3, warp_n = wid >> 2;
    int bm = blockIdx.y * 128, bn = blockIdx.x * 128;

    uint32_t sBase = smem_u32(dsm);

    int per = 0, nChunks;
    int seg = tokMask + 1;
    if (CAUSAL == 2) {
        int kl = (blockIdx.y + 1) * 128;
        if (kl > seg) kl = seg;
        per = kl >> 6;
        nChunks = (K / seg) * per;
    } else {
        nChunks = K >> 6;
    }

    auto k0_of = [&](int ci) -> int {
        if (CAUSAL == 2) return (ci / per) * seg + (ci % per) * 64;
        return ci * 64;
    };

    auto issue = [&](int stage, int k0) {
        // dedup segment wrap (chunks never straddle segment boundaries)
        int kA = (k0 < 2 * segK) ? k0 : k0 - 2 * segK;
        int kB = (k0 < segK) ? k0 : k0 - segK;
        uint32_t aB = sBase + (uint32_t)(stage * STAGEH) * 2;
        uint32_t bB = aB + BUFH * 2;
        #pragma unroll
        for (int u = tid; u < 1024; u += 256) {
            int row = u >> 3, c = u & 7;
            const __nv_bfloat16* src = A + (size_t)(bm + row) * lda + kA + c * 8;
            uint32_t dst = aB + (uint32_t)(row * SSTRIDE + c * 8) * 2;
            asm volatile("cp.async.cg.shared.global [%0], [%1], 16;"
                         :: "r"(dst), "l"(src));
        }
        #pragma unroll
        for (int u = tid; u < 1024; u += 256) {
            int row = u >> 3, c = u & 7;
            int ok = (bn + row) < N;
            const __nv_bfloat16* src = B + (size_t)(bn + (ok ? row : 0)) * ldb + kB + c * 8;
            uint32_t dst = bB + (uint32_t)(row * SSTRIDE + c * 8) * 2;
            int sz = ok ? 16 : 0;
            asm volatile("cp.async.cg.shared.global [%0], [%1], 16, %2;"
                         :: "r"(dst), "l"(src), "r"(sz));
        }
        asm volatile("cp.async.commit_group;" ::: "memory");
    };

    float acc[2][8][4];
    #pragma unroll
    for (int i = 0; i < 2; i++)
        #pragma unroll
        for (int j = 0; j < 8; j++)
            #pragma unroll
            for (int q = 0; q < 4; q++) acc[i][j][q] = 0.f;

    int g = lane >> 3, r = lane & 7;

    // prologue: 2 stages in flight (nChunks >= 2 at every call site)
    issue(0, k0_of(0));
    issue(1, k0_of(1));

    for (int ci = 0; ci < nChunks; ci++) {
        asm volatile("cp.async.wait_group 1;" ::: "memory");
        __syncthreads();

        uint32_t aB = sBase + (uint32_t)((ci % NSTAGE) * STAGEH) * 2;
        uint32_t bB = aB + BUFH * 2;
        #pragma unroll
        for (int kk = 0; kk < 64; kk += 16) {
            uint32_t afr[2][4];
            #pragma unroll
            for (int mt = 0; mt < 2; mt++) {
                int rowA = warp_m * 32 + mt * 16 + (g & 1) * 8 + r;
                int colA = kk + (g >> 1) * 8;
                uint32_t ad = aB + (uint32_t)(rowA * SSTRIDE + colA) * 2;
                LDMX4(afr[mt][0], afr[mt][1], afr[mt][2], afr[mt][3], ad);
            }
            #pragma unroll
            for (int ntp = 0; ntp < 4; ntp++) {
                int rowB = warp_n * 64 + ntp * 16 + (g >> 1) * 8 + r;
                int colB = kk + (g & 1) * 8;
                uint32_t bd = bB + (uint32_t)(rowB * SSTRIDE + colB) * 2;
                uint32_t b0, b1, b2, b3;
                LDMX4(b0, b1, b2, b3, bd);
                #pragma unroll
                for (int mt = 0; mt < 2; mt++) {
                    MMA16816(acc[mt][2 * ntp], afr[mt], b0, b1);
                    MMA16816(acc[mt][2 * ntp + 1], afr[mt], b2, b3);
                }
            }
        }

        if (ci + 2 < nChunks) issue((ci + 2) % NSTAGE, k0_of(ci + 2));
        else asm volatile("cp.async.commit_group;" ::: "memory");
    }

    // epilogue
    if (OUTBF16 == 0) {
        float* C = (float*)Cv + coff;
        #pragma unroll
        for (int mt = 0; mt < 2; mt++) {
            int row0 = bm + warp_m * 32 + mt * 16 + (lane >> 2);
            int orow = rowMul ? ((row0 & 1023) + (row0 >> 10) * rowMul) : row0;
            #pragma unroll
            for (int nt = 0; nt < 8; nt++) {
                int col = bn + warp_n * 64 + nt * 8 + (lane & 3) * 2;
                if (col < N) {
                    float* c0 = C + (size_t)orow * ldc + col;
                    *reinterpret_cast<float2*>(c0) =
                        make_float2(acc[mt][nt][0], acc[mt][nt][1]);
                    *reinterpret_cast<float2*>(c0 + 8LL * ldc) =
                        make_float2(acc[mt][nt][2], acc[mt][nt][3]);
                }
            }
        }
    } else {
        __nv_bfloat16* C = (__nv_bfloat16*)Cv + coff;
        #pragma unroll
        for (int mt = 0; mt < 2; mt++) {
            int row0 = bm + warp_m * 32 + mt * 16 + (lane >> 2);
            int orow = rowMul ? ((row0 & 1023) + (row0 >> 10) * rowMul) : row0;
            #pragma unroll
            for (int nt = 0; nt < 8; nt++) {
                int col = bn + warp_n * 64 + nt * 8 + (lane & 3) * 2;
                if (col < N) {
                    #pragma unroll
                    for (int rr = 0; rr < 2; rr++) {
                        __nv_bfloat16 h0, l0, h1, l1;
                        split2(acc[mt][nt][2 * rr + 0], h0, l0);
                        split2(acc[mt][nt][2 * rr + 1], h1, l1);
                        __nv_bfloat162 hp; hp.x = h0; hp.y = h1;
                        __nv_bfloat162 lp; lp.x = l0; lp.y = l1;
                        size_t base = (size_t)(orow + rr * 8) * ldc + col;
                        *reinterpret_cast<__nv_bfloat162*>(C + base) = hp;
                        *reinterpret_cast<__nv_bfloat162*>(C + base + segS) = lp;
                    }
                }
            }
        }
    }
}

// ---------------- conversions (dedup [hi|lo]) ----------------
// row-major fp32 -> bf16 [rows, 2K]: hi at k, lo at K+k
__global__ void convA_kernel(const float* __restrict__ in, __nv_bfloat16* __restrict__ out,
                             long long rows, int K, int ldin)
{
    long long idx = (long long)blockIdx.x * blockDim.x + threadIdx.x;
    long long total = rows * (long long)K;
    if (idx >= total) return;
    long long r = idx / K;
    int k = (int)(idx - r * K);
    float x = in[r * (long long)ldin + k];
    __nv_bfloat16 hi, lo; split2(x, hi, lo);
    __nv_bfloat16* o = out + r * (2LL * K);
    o[k] = hi;
    o[(long long)K + k] = lo;
}

// [K,N] row-major -> transposed K-major [N, 2K]: hi at k, lo at K+k
__global__ void convBT_kernel(const float* __restrict__ in, __nv_bfloat16* __restrict__ out,
                              int K, int N, int ldin, long long sIn, long long sOut)
{
    __shared__ float t[32][33];
    int zz = blockIdx.z;
    in  += (long long)zz * sIn;
    out += (long long)zz * sOut;
    int kb = blockIdx.x * 32, nb = blockIdx.y * 32;
    int tx = threadIdx.x, ty = threadIdx.y;   // 32 x 8
    #pragma unroll
    for (int i = 0; i < 32; i += 8)
        t[ty + i][tx] = in[(long long)(kb + ty + i) * ldin + nb + tx];
    __syncthreads();
    long long K2 = 2LL * K;
    #pragma unroll
    for (int i = 0; i < 32; i += 8) {
        int n = nb + ty + i;
        int k = kb + tx;
        float x = t[tx][ty + i];
        __nv_bfloat16 hi, lo; split2(x, hi, lo);
        __nv_bfloat16* o = out + (long long)n * K2;
        o[k] = hi; o[(long long)K + k] = lo;
    }
}

// ---------------- RMSNorm -> dedup bf16 (+ optional fp32 copy) ---------------
__global__ void rmsnorm_kernel(const float* __restrict__ in, const float* __restrict__ w,
                               float* __restrict__ out32, __nv_bfloat16* __restrict__ out16,
                               int cols, int ldin, int ldout, int ld2, int segS)
{
    long long row = blockIdx.x;
    const float* x = in + row * ldin;
    int tid = threadIdx.x;
    float ss = 0.f;
    for (int c = tid; c < cols; c += 256) { float v = x[c]; ss += v * v; }
    __shared__ float red[256];
    red[tid] = ss; __syncthreads();
    for (int s = 128; s > 0; s >>= 1) {
        if (tid < s) red[tid] += red[tid + s];
        __syncthreads();
    }
    float r = rsqrtf(red[0] / (float)cols + 1e-6f);
    __nv_bfloat16* o = out16 + row * (long long)ld2;
    for (int c = tid; c < cols; c += 256) {
        float v = x[c] * r * w[c];
        if (out32) out32[row * (long long)ldout + c] = v;
        __nv_bfloat16 hi, lo; split2(v, hi, lo);
        o[c] = hi;
        o[segS + c] = lo;
    }
}

// keys rope part from g_buf12 cols [2048,2112) -> e_keys (row stride 1152)
__global__ void rope_k_kernel(const float* __restrict__ buf12, const int* __restrict__ pos_ids,
                              __nv_bfloat16* __restrict__ ekeys)
{
    int gid = blockIdx.x * blockDim.x + threadIdx.x;
    if (gid >= MM * 32) return;
    int j = gid & 31;
    int row = gid >> 5;
    float pos = (float)pos_ids[row];
    float x0 = buf12[(long long)row * N12 + 2048 + 2 * j];
    float x1 = buf12[(long long)row * N12 + 2048 + 2 * j + 1];
    float o0, o1;
    rope_pair(x0, x1, pos, j, o0, o1);
    long long base = (long long)row * 1152 + KVL;
    store_exp(ekeys, base + j, 576, o0);
    store_exp(ekeys, base + 32 + j, 576, o1);
}

// q rope part -> e_query (row stride 1152)
__global__ void rope_q_kernel(const float* __restrict__ qpe, const int* __restrict__ pos_ids,
                              __nv_bfloat16* __restrict__ equery)
{
    int gid = blockIdx.x * blockDim.x + threadIdx.x;
    if (gid >= MM * HH * 32) return;
    int j = gid & 31;
    int h = (gid >> 5) & (HH - 1);
    int row = gid >> 10;
    int b = row >> 10;
    int s = row & (SS - 1);
    float pos = (float)pos_ids[row];
    float x0 = qpe[(long long)row * (HH * ROPE) + h * ROPE + 2 * j];
    float x1 = qpe[(long long)row * (HH * ROPE) + h * ROPE + 2 * j + 1];
    float o0, o1;
    rope_pair(x0, x1, pos, j, o0, o1);
    long long base = (((long long)(b * HH + h)) * SS + s) * 1152 + KVL;
    store_exp(equery, base + j, 576, o0);
    store_exp(equery, base + 32 + j, 576, o1);
}

// ---------------- fused causal softmax -> dedup bf16 probs ----------------
__global__ void softmax_kernel(const float* __restrict__ sc, __nv_bfloat16* __restrict__ out)
{
    int i = blockIdx.x;
    int z = blockIdx.y;
    long long base = ((long long)z * SS + i) * SS;
    long long ob = ((long long)z * SS + i) * 2048;
    int tid = threadIdx.x;
    const float scale = 0.07216878364870322f;  // 1/sqrt(192)
    int limit = ((i >> 7) + 1) << 7;           // 128-aligned causal tile limit

    float lm = -1e30f;
    float v[4];
    int cnt = 0;
    for (int j = tid; j <= i; j += 256) {
        v[cnt] = sc[base + j];
        lm = fmaxf(lm, v[cnt]);
        cnt++;
    }
    __shared__ float red[256];
    red[tid] = lm; __syncthreads();
    for (int s = 128; s > 0; s >>= 1) {
        if (tid < s) red[tid] = fmaxf(red[tid], red[tid + s]);
        __syncthreads();
    }
    float m = red[0] * scale;
    __syncthreads();

    float ls = 0.f;
    #pragma unroll
    for (int q = 0; q < 4; q++) {
        if (q < cnt) {
            v[q] = expf(v[q] * scale - m);
            ls += v[q];
        }
    }
    red[tid] = ls; __syncthreads();
    for (int s = 128; s > 0; s >>= 1) {
        if (tid < s) red[tid] += red[tid + s];
        __syncthreads();
    }
    float inv = 1.f / red[0];

    int q = 0;
    for (int j = tid; j < limit; j += 256) {
        float p = (j <= i) ? v[q] * inv : 0.f;
        q++;
        __nv_bfloat16 hi, lo; split2(p, hi, lo);
        out[ob + j] = hi;
        out[ob + 1024 + j] = lo;
    }
}

// ---------------- launch ----------------
static inline int cdiv(long long a, int b) { return (int)((a + b - 1) / b); }

extern "C" void kernel_launch(void* const* d_in, const int* in_sizes, int n_in,
                              void* d_out, int out_size)
{
    const float* hidden    = (const float*)d_in[0];
    const int*   pos       = (const int*)d_in[2];
    const float* w_q_a     = (const float*)d_in[3];
    const float* q_a_ln_w  = (const float*)d_in[4];
    const float* q_rope    = (const float*)d_in[5];
    const float* fusedqk   = (const float*)d_in[6];
    const float* w_kv_a    = (const float*)d_in[7];
    const float* kv_a_ln_w = (const float*)d_in[8];
    const float* v_up      = (const float*)d_in[9];
    const float* w_o       = (const float*)d_in[10];
    float* out = (float*)d_out;

    float *buf12, *bufA, *keys, *scores;
    cudaGetSymbolAddress((void**)&buf12,  g_buf12);
    cudaGetSymbolAddress((void**)&bufA,   g_bufA);
    cudaGetSymbolAddress((void**)&keys,   g_keys);
    cudaGetSymbolAddress((void**)&scores, g_scores);

    __nv_bfloat16 *ehid, *ew12, *eqa, *eqr, *efqk, *equery, *ekeys,
                  *escores, *ekva, *ectx, *evup, *eatt, *ewo;
    cudaGetSymbolAddress((void**)&ehid,    e_hidden);
    cudaGetSymbolAddress((void**)&ew12,    e_w12);
    cudaGetSymbolAddress((void**)&eqa,     e_qa);
    cudaGetSymbolAddress((void**)&eqr,     e_qrope);
    cudaGetSymbolAddress((void**)&efqk,    e_fqk);
    cudaGetSymbolAddress((void**)&equery,  e_query);
    cudaGetSymbolAddress((void**)&ekeys,   e_keys);
    cudaGetSymbolAddress((void**)&escores, e_scores);
    cudaGetSymbolAddress((void**)&ekva,    e_kva);
    cudaGetSymbolAddress((void**)&ectx,    e_ctx);
    cudaGetSymbolAddress((void**)&evup,    e_vup);
    cudaGetSymbolAddress((void**)&eatt,    e_attout);
    cudaGetSymbolAddress((void**)&ewo,     e_wo);

    cudaFuncSetAttribute(mma_gemm<0,0>, cudaFuncAttributeMaxDynamicSharedMemorySize, GSMEM_SZ);
    cudaFuncSetAttribute(mma_gemm<0,1>, cudaFuncAttributeMaxDynamicSharedMemorySize, GSMEM_SZ);
    cudaFuncSetAttribute(mma_gemm<1,0>, cudaFuncAttributeMaxDynamicSharedMemorySize, GSMEM_SZ);
    cudaFuncSetAttribute(mma_gemm<2,1>, cudaFuncAttributeMaxDynamicSharedMemorySize, GSMEM_SZ);

    dim3 tb(32, 8);

    // ---- launches 0-2: conversions needed by the first GEMM ----
    convA_kernel<<<cdiv((long long)2048 * 4096, 256), 256>>>(hidden, ehid, 2048, 4096, 4096);
    convBT_kernel<<<dim3(128, 48, 1), tb>>>(w_q_a,  ew12,  4096, 1536, 1536, 0, 0);
    convBT_kernel<<<dim3(128, 18, 1), tb>>>(w_kv_a, ew12 + (size_t)1536 * 8192,
                                            4096, 576, 576, 0, 0);

    // ---- launch 3 (ncu target): [qa_raw | ckv] = hidden @ [w_q_a|w_kv_a] ----
    mma_gemm<0, 0><<<dim3(17, 16, 1), 256, GSMEM_SZ>>>(ehid, ew12, buf12,
        2048, N12, 12288, 8192, 8192, N12, 0, 4096, 0, 0, 0, 0, 0, 0, 1, 0, 0);

    // ---- rmsnorms + rope_k ----
    rmsnorm_kernel<<<2048, 256>>>(buf12, q_a_ln_w, nullptr, eqa, 1536, N12, 0, 3072, 1536);
    rmsnorm_kernel<<<2048, 256>>>(buf12 + 1536, kv_a_ln_w, keys, ekeys, 512, N12, 512, 1152, 576);
    rope_k_kernel<<<(MM * 32) / 256, 256>>>(buf12, pos, ekeys);

    // ---- kva K-major transpose for ctx GEMM ----
    convBT_kernel<<<dim3(32, 16, 2), tb>>>(keys, ekva, 1024, 512, 512,
        (long long)1024 * 512, (long long)512 * 2048);

    // ---- q_rope weight conversion, then qpe_raw = qa @ q_rope (fp32) ----
    convBT_kernel<<<dim3(48, 64, 1), tb>>>(q_rope, eqr, 1536, 2048, 2048, 0, 0);
    mma_gemm<0, 0><<<dim3(16, 16, 1), 256, GSMEM_SZ>>>(eqa, eqr, bufA,
        2048, 2048, 4608, 3072, 3072, 2048, 0, 1536, 0, 0, 0, 0, 0, 0, 1, 0, 0);

    // ---- rope(q) -> e_query rope cols ----
    rope_q_kernel<<<(MM * HH * 32) / 256, 256>>>(bufA, pos, equery);

    // ---- fusedqk conversion, then q_abs = qa @ fusedqk[h] -> e_query[:512] ----
    convBT_kernel<<<dim3(48, 16, 32), tb>>>(fusedqk, efqk, 1536, 512, 512,
        (long long)1536 * 512, (long long)512 * 3072);
    mma_gemm<0, 1><<<dim3(4, 16, 32), 256, GSMEM_SZ>>>(eqa, efqk, equery,
        2048, 512, 4608, 3072, 3072, 1152, 576, 1536,
        0, 0,
        0, (long long)512 * 3072,
        0, (long long)1024 * 1152, 32, 0, 32768);

    // ---- weight conversions for later stages ----
    convBT_kernel<<<dim3(16, 4, 32),   tb>>>(v_up, evup, 512, 128, 128,
        (long long)512 * 128, (long long)128 * 1024);
    convBT_kernel<<<dim3(128, 128, 1), tb>>>(w_o, ewo, 4096, 4096, 4096, 0, 0);

    // ---- scores = query @ keys^T (fp32, causal tile skip) ----
    mma_gemm<1, 0><<<dim3(8, 8, 64), 256, GSMEM_SZ>>>(equery, ekeys, scores,
        1024, 1024, 1728, 1152, 1152, 1024, 0, 576,
        (long long)32 * 1024 * 1152, (long long)1024 * 1152,
        (long long)1024 * 1152, 0,
        (long long)32 * 1024 * 1024, (long long)1024 * 1024, 32, 0, 0);

    // ---- fused softmax -> e_scores (dedup, 128-aligned zero fill) ----
    softmax_kernel<<<dim3(1024, 64), 256>>>(scores, escores);

    // ---- ctx = probs @ kva -> e_ctx (bf16 epilogue, chunk skip) ----
    mma_gemm<2, 1><<<dim3(4, 8, 64), 256, GSMEM_SZ>>>(escores, ekva, ectx,
        1024, 512, 3072, 2048, 2048, 1024, 512, 1024,
        (long long)32 * 1024 * 2048, (long long)1024 * 2048,
        (long long)512 * 2048, 0,
        (long long)32 * 1024 * 1024, (long long)1024 * 1024, 32, 1023, 0);

    // ---- attout = ctx @ v_up[h] -> e_attout (bf16 epilogue) ----
    mma_gemm<0, 1><<<dim3(1, 8, 64), 256, GSMEM_SZ>>>(ectx, evup, eatt,
        1024, 128, 1536, 1024, 1024, 8192, 4096, 512,
        (long long)32 * 1024 * 1024, (long long)1024 * 1024,
        0, (long long)128 * 1024,
        (long long)1024 * 8192, 128, 32, 0, 0);

    // ---- out = attout @ w_o (fp32) ----
    mma_gemm<0, 0><<<dim3(32, 16, 1), 256, GSMEM_SZ>>>(eatt, ewo, out,
        2048, 4096, 12288, 8192, 8192, 4096, 0, 4096, 0, 0, 0, 0, 0, 0, 1, 0, 0);
}